// round 11
// baseline (speedup 1.0000x reference)
#include <cuda_runtime.h>
#include <cuda_bf16.h>
#include <cuda_fp16.h>
#include <stdint.h>

namespace {

constexpr int Bb = 4, Ss = 2048, Hh = 16, Dd = 64;
constexpr int BM = 64, BN = 64;
constexpr int KP = 36;            // u32 per sK row: frag bank = 4g+c, conflict-free
constexpr int VP = 72;            // u32 per sV row-pair: frag bank = 8c+g, conflict-free
constexpr float SCALE = 0.125f;
constexpr float LOG2E = 1.4426950408889634f;
constexpr float NEGINF = -1e30f;

// fp16 scratch (pre-converted, re-laid-out), written by pre-pass kernels each call
__device__ __half   g_Qh[(size_t)Bb * Hh * Ss * Dd];        // [b][h][s][d]
__device__ __half   g_Kh[(size_t)Bb * Hh * Ss * Dd];        // [b][h][s][d]
__device__ uint32_t g_Vp[(size_t)Bb * Hh * (Ss/2) * Dd];    // [b][h][rp][d] f16x2(v[2rp],v[2rp+1])

__device__ __forceinline__ uint32_t packf16x2(float lo, float hi) {
    uint32_t r;
    asm("cvt.rn.f16x2.f32 %0, %1, %2;" : "=r"(r) : "f"(hi), "f"(lo));
    return r;
}
__device__ __forceinline__ uint32_t ex2h2(uint32_t x) {
    uint32_t r;
    asm("ex2.approx.f16x2 %0, %1;" : "=r"(r) : "r"(x));
    return r;
}
__device__ __forceinline__ uint32_t smem_u32(const void* p) {
    uint32_t a;
    asm("{ .reg .u64 t; cvta.to.shared.u64 t, %1; cvt.u32.u64 %0, t; }" : "=r"(a) : "l"(p));
    return a;
}
__device__ __forceinline__ void cpa16(uint32_t dst, const void* src) {
    asm volatile("cp.async.cg.shared.global [%0], [%1], 16;" :: "r"(dst), "l"(src));
}

__device__ __forceinline__ void mma_f16(float c[4], const uint32_t a[4], const uint32_t b[2]) {
    asm volatile(
        "mma.sync.aligned.m16n8k16.row.col.f32.f16.f16.f32 "
        "{%0,%1,%2,%3}, {%4,%5,%6,%7}, {%8,%9}, {%0,%1,%2,%3};"
        : "+f"(c[0]), "+f"(c[1]), "+f"(c[2]), "+f"(c[3])
        : "r"(a[0]), "r"(a[1]), "r"(a[2]), "r"(a[3]), "r"(b[0]), "r"(b[1]));
}

// ---- pre-pass: fp32 [b][s][h][d] -> fp16 [b][h][s][d] ----
__global__ void __launch_bounds__(256)
cvt_qk_kernel(const float* __restrict__ src, int which)
{
    __half* dst = which ? g_Kh : g_Qh;
    const int i   = blockIdx.x * 256 + threadIdx.x;   // output-major
    const int d4i = i & 15;
    const int s   = (i >> 4) & 2047;
    const int h   = (i >> 15) & 15;
    const int b   = i >> 19;
    const float4 f = *(const float4*)(src + (((size_t)(b * Ss + s) * Hh + h) * Dd + d4i * 4));
    uint2 w;
    w.x = packf16x2(f.x, f.y);
    w.y = packf16x2(f.z, f.w);
    *(uint2*)(dst + (((size_t)(b * Hh + h) * Ss + s) * Dd + d4i * 4)) = w;
}

// ---- pre-pass: V fp32 [b][s][h][d] -> f16x2 row-pair interleave [b][h][rp][d] ----
__global__ void __launch_bounds__(256)
cvt_v_kernel(const float* __restrict__ v)
{
    const int i   = blockIdx.x * 256 + threadIdx.x;
    const int d4i = i & 15;
    const int rp  = (i >> 4) & 1023;
    const int h   = (i >> 14) & 15;
    const int b   = i >> 18;
    const float* base = v + (((size_t)(b * Ss + 2 * rp) * Hh + h) * Dd + d4i * 4);
    const float4 f0 = *(const float4*)(base);
    const float4 f1 = *(const float4*)(base + Hh * Dd);
    uint4 w;
    w.x = packf16x2(f0.x, f1.x);
    w.y = packf16x2(f0.y, f1.y);
    w.z = packf16x2(f0.z, f1.z);
    w.w = packf16x2(f0.w, f1.w);
    *(uint4*)(g_Vp + (((size_t)(b * Hh + h) * (Ss/2) + rp) * Dd + d4i * 4)) = w;
}

// ---- main kernel ----
__global__ void __launch_bounds__(128, 3)
fa_kernel(const float* __restrict__ bias, float* __restrict__ out)
{
    __shared__ __align__(16) uint32_t sK[2][BN * KP];       // double-buffered, f16x2 d-pairs
    __shared__ __align__(16) uint32_t sV[2][(BN/2) * VP];   // double-buffered, f16x2 row pairs

    const int tid  = threadIdx.x;
    const int lane = tid & 31;
    const int wid  = tid >> 5;
    const int g    = lane >> 2;
    const int c    = lane & 3;

    const int idx = blockIdx.x;
    const int b   = idx & 3;
    const int h   = (idx >> 2) & 15;
    const int qt  = (Ss / BM - 1) - (idx >> 6);
    const int qrow = qt * BM;

    const int r0 = qrow + wid * 16 + g;
    const int r1 = r0 + 8;

    const uint32_t sKa[2] = { smem_u32(&sK[0][0]), smem_u32(&sK[1][0]) };
    const uint32_t sVa[2] = { smem_u32(&sV[0][0]), smem_u32(&sV[1][0]) };

    const char* kbase = (const char*)(g_Kh + ((size_t)(b * Hh + h) * Ss) * Dd);
    const char* vbase = (const char*)(g_Vp + ((size_t)(b * Hh + h) * (Ss/2)) * Dd);

    // ---- Q fragments (f16) loaded once from pre-converted gmem ----
    uint32_t qa[4][4];
    {
        const __half* qh0 = g_Qh + ((size_t)(b * Hh + h) * Ss + r0) * Dd;
        const __half* qh1 = g_Qh + ((size_t)(b * Hh + h) * Ss + r1) * Dd;
#pragma unroll
        for (int ks = 0; ks < 4; ks++) {
            const int d0 = ks * 16 + 2 * c;
            qa[ks][0] = *(const uint32_t*)(qh0 + d0);
            qa[ks][1] = *(const uint32_t*)(qh1 + d0);
            qa[ks][2] = *(const uint32_t*)(qh0 + d0 + 8);
            qa[ks][3] = *(const uint32_t*)(qh1 + d0 + 8);
        }
    }

    float oacc[8][4];
#pragma unroll
    for (int i = 0; i < 8; i++) {
        oacc[i][0] = 0.f; oacc[i][1] = 0.f; oacc[i][2] = 0.f; oacc[i][3] = 0.f;
    }
    float lacc[4] = {0.f, 0.f, 0.f, 0.f};
    float m0 = NEGINF, m1 = NEGINF;

    const uint32_t onesw = (g == 0) ? 0x3C003C00u : 0u;
    const uint32_t onesb[2] = {onesw, onesw};

    const float* biasr0 = bias + ((size_t)h * Ss + r0) * Ss;
    const float* biasr1 = bias + ((size_t)h * Ss + r1) * Ss;

    // issue cp.async loads for tile jt into buffer pb
    auto issue_tile = [&](int jt, int pb) {
        const char* kb = kbase + (size_t)jt * BN * Dd * 2;        // 64 rows x 128B
        const char* vb = vbase + (size_t)jt * (BN/2) * Dd * 4;    // 32 rps x 256B
#pragma unroll
        for (int it = 0; it < 4; it++) {
            const int gk = it * 128 + tid;
            const int n = gk >> 3, col = gk & 7;
            cpa16(sKa[pb] + n * 144 + col * 16, kb + n * 128 + col * 16);
        }
#pragma unroll
        for (int it = 0; it < 4; it++) {
            const int gv = it * 128 + tid;
            const int rp = gv >> 4, col = gv & 15;
            cpa16(sVa[pb] + rp * 288 + col * 16, vb + rp * 256 + col * 16);
        }
        asm volatile("cp.async.commit_group;");
    };

    issue_tile(0, 0);   // prologue

    for (int j = 0; j <= qt; j++) {
        const int p = j & 1;
        __syncthreads();                       // protect buf p^1 from overwrite
        issue_tile((j < qt) ? (j + 1) : qt, p ^ 1);
        asm volatile("cp.async.wait_group 1;");
        __syncthreads();                       // tile j visible to all

        const uint32_t* sKp = sK[p];
        const uint32_t* sVp = sV[p];

        // ---- bias prefetch (hidden behind QK mma) ----
        const int kcb = j * BN;
        float2 bpre0[8], bpre1[8];
#pragma unroll
        for (int nf = 0; nf < 8; nf++) {
            const int kc = kcb + nf * 8 + 2 * c;
            bpre0[nf] = __ldg((const float2*)(biasr0 + kc));
            bpre1[nf] = __ldg((const float2*)(biasr1 + kc));
        }

        // ---- S = Q K^T ----
        float sacc[8][4];
#pragma unroll
        for (int nf = 0; nf < 8; nf++) {
            sacc[nf][0] = 0.f; sacc[nf][1] = 0.f; sacc[nf][2] = 0.f; sacc[nf][3] = 0.f;
#pragma unroll
            for (int ks = 0; ks < 4; ks++) {
                const uint32_t* kp = &sKp[(nf * 8 + g) * KP + ks * 8 + c];
                uint32_t bfr[2];
                bfr[0] = kp[0];
                bfr[1] = kp[4];
                mma_f16(sacc[nf], qa[ks], bfr);
            }
        }

        // ---- scale + bias + causal mask ----
        const bool diag = (j == qt);
#pragma unroll
        for (int nf = 0; nf < 8; nf++) {
            const int kc = kcb + nf * 8 + 2 * c;
            sacc[nf][0] = sacc[nf][0] * SCALE + bpre0[nf].x;
            sacc[nf][1] = sacc[nf][1] * SCALE + bpre0[nf].y;
            sacc[nf][2] = sacc[nf][2] * SCALE + bpre1[nf].x;
            sacc[nf][3] = sacc[nf][3] * SCALE + bpre1[nf].y;
            if (diag) {
                if (kc     > r0) sacc[nf][0] = NEGINF;
                if (kc + 1 > r0) sacc[nf][1] = NEGINF;
                if (kc     > r1) sacc[nf][2] = NEGINF;
                if (kc + 1 > r1) sacc[nf][3] = NEGINF;
            }
        }

        // ---- online softmax: maxes only ----
        float rm0 = NEGINF, rm1 = NEGINF;
#pragma unroll
        for (int nf = 0; nf < 8; nf++) {
            rm0 = fmaxf(rm0, fmaxf(sacc[nf][0], sacc[nf][1]));
            rm1 = fmaxf(rm1, fmaxf(sacc[nf][2], sacc[nf][3]));
        }
        rm0 = fmaxf(rm0, __shfl_xor_sync(0xffffffffu, rm0, 1));
        rm0 = fmaxf(rm0, __shfl_xor_sync(0xffffffffu, rm0, 2));
        rm1 = fmaxf(rm1, __shfl_xor_sync(0xffffffffu, rm1, 1));
        rm1 = fmaxf(rm1, __shfl_xor_sync(0xffffffffu, rm1, 2));

        const float nm0 = fmaxf(m0, rm0), nm1 = fmaxf(m1, rm1);
        const float a0 = __expf(m0 - nm0), a1 = __expf(m1 - nm1);
        m0 = nm0; m1 = nm1;
        const float mL0 = nm0 * LOG2E, mL1 = nm1 * LOG2E;

        lacc[0] *= a0; lacc[1] *= a0; lacc[2] *= a1; lacc[3] *= a1;
#pragma unroll
        for (int df = 0; df < 8; df++) {
            oacc[df][0] *= a0; oacc[df][1] *= a0;
            oacc[df][2] *= a1; oacc[df][3] *= a1;
        }

        // ---- P = ex2(s*log2e - m*log2e); O += P V; l += P·1 ----
#pragma unroll
        for (int t = 0; t < 4; t++) {
            uint32_t af[4];
            af[0] = ex2h2(packf16x2(fmaf(sacc[2*t][0],   LOG2E, -mL0),
                                    fmaf(sacc[2*t][1],   LOG2E, -mL0)));
            af[1] = ex2h2(packf16x2(fmaf(sacc[2*t][2],   LOG2E, -mL1),
                                    fmaf(sacc[2*t][3],   LOG2E, -mL1)));
            af[2] = ex2h2(packf16x2(fmaf(sacc[2*t+1][0], LOG2E, -mL0),
                                    fmaf(sacc[2*t+1][1], LOG2E, -mL0)));
            af[3] = ex2h2(packf16x2(fmaf(sacc[2*t+1][2], LOG2E, -mL1),
                                    fmaf(sacc[2*t+1][3], LOG2E, -mL1)));

            mma_f16(lacc, af, onesb);

            const int rpb = t * 8 + c;
#pragma unroll
            for (int df = 0; df < 8; df++) {
                const uint32_t* vh = &sVp[rpb * VP + df * 8 + g];
                uint32_t bfr[2];
                bfr[0] = vh[0];
                bfr[1] = vh[4 * VP];
                mma_f16(oacc[df], af, bfr);
            }
        }
    }

    asm volatile("cp.async.wait_group 0;");   // drain the tail dup prefetch

    // ---- epilogue ----
    const float l0 = __shfl_sync(0xffffffffu, lacc[0], lane & ~3);
    const float l1 = __shfl_sync(0xffffffffu, lacc[2], lane & ~3);
    const float inv0 = 1.0f / l0;
    const float inv1 = 1.0f / l1;

    float* o0 = out + ((size_t)(b * Ss + r0) * Hh + h) * Dd;
    float* o1 = out + ((size_t)(b * Ss + r1) * Hh + h) * Dd;
#pragma unroll
    for (int df = 0; df < 8; df++) {
        const int dc = df * 8 + 2 * c;
        float2 w0, w1;
        w0.x = oacc[df][0] * inv0; w0.y = oacc[df][1] * inv0;
        w1.x = oacc[df][2] * inv1; w1.y = oacc[df][3] * inv1;
        *(float2*)(o0 + dc) = w0;
        *(float2*)(o1 + dc) = w1;
    }
}

} // namespace

extern "C" void kernel_launch(void* const* d_in, const int* in_sizes, int n_in,
                              void* d_out, int out_size)
{
    const float* q    = (const float*)d_in[0];
    const float* k    = (const float*)d_in[1];
    const float* v    = (const float*)d_in[2];
    const float* bias = (const float*)d_in[3];
    float* out        = (float*)d_out;

    cvt_qk_kernel<<<(Bb * Hh * Ss * (Dd/4)) / 256, 256>>>(q, 0);
    cvt_qk_kernel<<<(Bb * Hh * Ss * (Dd/4)) / 256, 256>>>(k, 1);
    cvt_v_kernel <<<(Bb * Hh * (Ss/2) * (Dd/4)) / 256, 256>>>(v);

    const dim3 grid(Bb * Hh * (Ss / BM));  // 2048 CTAs, batch fastest-varying
    fa_kernel<<<grid, 128>>>(bias, out);
}

// round 12
// speedup vs baseline: 1.0864x; 1.0864x over previous
#include <cuda_runtime.h>
#include <cuda_bf16.h>
#include <cuda_fp16.h>
#include <stdint.h>

namespace {

constexpr int Bb = 4, Ss = 2048, Hh = 16, Dd = 64;
constexpr int BM = 64, BN = 64;
constexpr int KP = 36;            // u32 per sK row: frag bank = 4g+c, conflict-free
constexpr int VP = 72;            // u32 per sV row-pair: frag bank = 8c+g, conflict-free
constexpr int NSTG = 3;           // pipeline depth
constexpr float SCALE = 0.125f;
constexpr float LOG2E = 1.4426950408889634f;
constexpr float NEGINF = -1e30f;

// fp16 scratch (pre-converted K/V), written by the fused pre-pass each call
__device__ __half   g_Kh[(size_t)Bb * Hh * Ss * Dd];        // [b][h][s][d]
__device__ uint32_t g_Vp[(size_t)Bb * Hh * (Ss/2) * Dd];    // [b][h][rp][d] f16x2(v[2rp],v[2rp+1])

__device__ __forceinline__ uint32_t packf16x2(float lo, float hi) {
    uint32_t r;
    asm("cvt.rn.f16x2.f32 %0, %1, %2;" : "=r"(r) : "f"(hi), "f"(lo));
    return r;
}
__device__ __forceinline__ uint32_t ex2h2(uint32_t x) {
    uint32_t r;
    asm("ex2.approx.f16x2 %0, %1;" : "=r"(r) : "r"(x));
    return r;
}
__device__ __forceinline__ uint32_t smem_u32(const void* p) {
    uint32_t a;
    asm("{ .reg .u64 t; cvta.to.shared.u64 t, %1; cvt.u32.u64 %0, t; }" : "=r"(a) : "l"(p));
    return a;
}
__device__ __forceinline__ void cpa16(uint32_t dst, const void* src) {
    asm volatile("cp.async.cg.shared.global [%0], [%1], 16;" :: "r"(dst), "l"(src));
}

__device__ __forceinline__ void mma_f16(float c[4], const uint32_t a[4], const uint32_t b[2]) {
    asm volatile(
        "mma.sync.aligned.m16n8k16.row.col.f32.f16.f16.f32 "
        "{%0,%1,%2,%3}, {%4,%5,%6,%7}, {%8,%9}, {%0,%1,%2,%3};"
        : "+f"(c[0]), "+f"(c[1]), "+f"(c[2]), "+f"(c[3])
        : "r"(a[0]), "r"(a[1]), "r"(a[2]), "r"(a[3]), "r"(b[0]), "r"(b[1]));
}

// ---- fused pre-pass: K -> fp16 [b][h][s][d]; V -> f16x2 row-pair [b][h][rp][d] ----
constexpr int KBLKS = (Bb * Hh * Ss * (Dd / 4)) / 256;        // 8192
constexpr int VBLKS = (Bb * Hh * (Ss / 2) * (Dd / 4)) / 256;  // 4096

__global__ void __launch_bounds__(256)
cvt_kv_kernel(const float* __restrict__ k, const float* __restrict__ v)
{
    if (blockIdx.x < KBLKS) {
        const int i   = blockIdx.x * 256 + threadIdx.x;
        const int d4i = i & 15;
        const int s   = (i >> 4) & 2047;
        const int h   = (i >> 15) & 15;
        const int b   = i >> 19;
        const float4 f = *(const float4*)(k + (((size_t)(b * Ss + s) * Hh + h) * Dd + d4i * 4));
        uint2 w;
        w.x = packf16x2(f.x, f.y);
        w.y = packf16x2(f.z, f.w);
        *(uint2*)(g_Kh + (((size_t)(b * Hh + h) * Ss + s) * Dd + d4i * 4)) = w;
    } else {
        const int i   = (blockIdx.x - KBLKS) * 256 + threadIdx.x;
        const int d4i = i & 15;
        const int rp  = (i >> 4) & 1023;
        const int h   = (i >> 14) & 15;
        const int b   = i >> 18;
        const float* base = v + (((size_t)(b * Ss + 2 * rp) * Hh + h) * Dd + d4i * 4);
        const float4 f0 = *(const float4*)(base);
        const float4 f1 = *(const float4*)(base + Hh * Dd);
        uint4 w;
        w.x = packf16x2(f0.x, f1.x);
        w.y = packf16x2(f0.y, f1.y);
        w.z = packf16x2(f0.z, f1.z);
        w.w = packf16x2(f0.w, f1.w);
        *(uint4*)(g_Vp + (((size_t)(b * Hh + h) * (Ss/2) + rp) * Dd + d4i * 4)) = w;
    }
}

// ---- main kernel ----
__global__ void __launch_bounds__(128, 3)
fa_kernel(const float* __restrict__ q, const float* __restrict__ bias,
          float* __restrict__ out)
{
    __shared__ __align__(16) uint32_t sK[NSTG][BN * KP];
    __shared__ __align__(16) uint32_t sV[NSTG][(BN/2) * VP];

    const int tid  = threadIdx.x;
    const int lane = tid & 31;
    const int wid  = tid >> 5;
    const int g    = lane >> 2;
    const int c    = lane & 3;

    const int idx = blockIdx.x;
    const int b   = idx & 3;
    const int h   = (idx >> 2) & 15;
    const int qt  = (Ss / BM - 1) - (idx >> 6);
    const int qrow = qt * BM;

    const int r0 = qrow + wid * 16 + g;
    const int r1 = r0 + 8;

    uint32_t sKa[NSTG], sVa[NSTG];
#pragma unroll
    for (int s = 0; s < NSTG; s++) { sKa[s] = smem_u32(&sK[s][0]); sVa[s] = smem_u32(&sV[s][0]); }

    const char* kbase = (const char*)(g_Kh + ((size_t)(b * Hh + h) * Ss) * Dd);
    const char* vbase = (const char*)(g_Vp + ((size_t)(b * Hh + h) * (Ss/2)) * Dd);

    // issue cp.async loads for tile jt into stage pb (one commit group)
    auto issue_tile = [&](int jt, int pb) {
        const char* kb = kbase + (size_t)jt * BN * Dd * 2;        // 64 rows x 128B
        const char* vb = vbase + (size_t)jt * (BN/2) * Dd * 4;    // 32 rps x 256B
#pragma unroll
        for (int it = 0; it < 4; it++) {
            const int gk = it * 128 + tid;
            const int n = gk >> 3, col = gk & 7;
            cpa16(sKa[pb] + n * 144 + col * 16, kb + n * 128 + col * 16);
        }
#pragma unroll
        for (int it = 0; it < 4; it++) {
            const int gv = it * 128 + tid;
            const int rp = gv >> 4, col = gv & 15;
            cpa16(sVa[pb] + rp * 288 + col * 16, vb + rp * 256 + col * 16);
        }
        asm volatile("cp.async.commit_group;");
    };

    // prologue: start tiles 0 and 1 (clamped)
    issue_tile(0, 0);
    issue_tile((qt >= 1) ? 1 : qt, 1 % NSTG);

    // ---- Q fragments: fp32 load + pack (once) ----
    uint32_t qa[4][4];
    {
        const float* q0 = q + ((size_t)(b * Ss + r0) * Hh + h) * Dd;
        const float* q1 = q + ((size_t)(b * Ss + r1) * Hh + h) * Dd;
#pragma unroll
        for (int ks = 0; ks < 4; ks++) {
            const int d0 = ks * 16 + 2 * c;
            const float2 a00 = *(const float2*)(q0 + d0);
            const float2 a01 = *(const float2*)(q1 + d0);
            const float2 a10 = *(const float2*)(q0 + d0 + 8);
            const float2 a11 = *(const float2*)(q1 + d0 + 8);
            qa[ks][0] = packf16x2(a00.x, a00.y);
            qa[ks][1] = packf16x2(a01.x, a01.y);
            qa[ks][2] = packf16x2(a10.x, a10.y);
            qa[ks][3] = packf16x2(a11.x, a11.y);
        }
    }

    float oacc[8][4];
#pragma unroll
    for (int i = 0; i < 8; i++) {
        oacc[i][0] = 0.f; oacc[i][1] = 0.f; oacc[i][2] = 0.f; oacc[i][3] = 0.f;
    }
    float lacc[4] = {0.f, 0.f, 0.f, 0.f};
    float m0 = NEGINF, m1 = NEGINF;

    const uint32_t onesw = (g == 0) ? 0x3C003C00u : 0u;
    const uint32_t onesb[2] = {onesw, onesw};

    const float* biasr0 = bias + ((size_t)h * Ss + r0) * Ss;
    const float* biasr1 = bias + ((size_t)h * Ss + r1) * Ss;

    for (int j = 0; j <= qt; j++) {
        const int p = j % NSTG;
        asm volatile("cp.async.wait_group 1;");   // tile j arrived (j+1 may be pending)
        __syncthreads();                          // all warps done with stage (j+2)%NSTG reads

        // start tile j+2 into the freed stage
        issue_tile((j + 2 <= qt) ? (j + 2) : qt, (j + 2) % NSTG);

        const uint32_t* sKp = sK[p];
        const uint32_t* sVp = sV[p];

        // ---- bias prefetch (hidden behind QK mma) ----
        const int kcb = j * BN;
        float2 bpre0[8], bpre1[8];
#pragma unroll
        for (int nf = 0; nf < 8; nf++) {
            const int kc = kcb + nf * 8 + 2 * c;
            bpre0[nf] = __ldg((const float2*)(biasr0 + kc));
            bpre1[nf] = __ldg((const float2*)(biasr1 + kc));
        }

        // ---- S = Q K^T ----
        float sacc[8][4];
#pragma unroll
        for (int nf = 0; nf < 8; nf++) {
            sacc[nf][0] = 0.f; sacc[nf][1] = 0.f; sacc[nf][2] = 0.f; sacc[nf][3] = 0.f;
#pragma unroll
            for (int ks = 0; ks < 4; ks++) {
                const uint32_t* kp = &sKp[(nf * 8 + g) * KP + ks * 8 + c];
                uint32_t bfr[2];
                bfr[0] = kp[0];
                bfr[1] = kp[4];
                mma_f16(sacc[nf], qa[ks], bfr);
            }
        }

        // ---- scale + bias + causal mask ----
        const bool diag = (j == qt);
#pragma unroll
        for (int nf = 0; nf < 8; nf++) {
            const int kc = kcb + nf * 8 + 2 * c;
            sacc[nf][0] = sacc[nf][0] * SCALE + bpre0[nf].x;
            sacc[nf][1] = sacc[nf][1] * SCALE + bpre0[nf].y;
            sacc[nf][2] = sacc[nf][2] * SCALE + bpre1[nf].x;
            sacc[nf][3] = sacc[nf][3] * SCALE + bpre1[nf].y;
            if (diag) {
                if (kc     > r0) sacc[nf][0] = NEGINF;
                if (kc + 1 > r0) sacc[nf][1] = NEGINF;
                if (kc     > r1) sacc[nf][2] = NEGINF;
                if (kc + 1 > r1) sacc[nf][3] = NEGINF;
            }
        }

        // ---- online softmax: maxes ----
        float rm0 = NEGINF, rm1 = NEGINF;
#pragma unroll
        for (int nf = 0; nf < 8; nf++) {
            rm0 = fmaxf(rm0, fmaxf(sacc[nf][0], sacc[nf][1]));
            rm1 = fmaxf(rm1, fmaxf(sacc[nf][2], sacc[nf][3]));
        }
        rm0 = fmaxf(rm0, __shfl_xor_sync(0xffffffffu, rm0, 1));
        rm0 = fmaxf(rm0, __shfl_xor_sync(0xffffffffu, rm0, 2));
        rm1 = fmaxf(rm1, __shfl_xor_sync(0xffffffffu, rm1, 1));
        rm1 = fmaxf(rm1, __shfl_xor_sync(0xffffffffu, rm1, 2));

        const float nm0 = fmaxf(m0, rm0), nm1 = fmaxf(m1, rm1);

        // skip rescale when no lane's max moved (a==1 exactly -> identity)
        if (__any_sync(0xffffffffu, (nm0 > m0) | (nm1 > m1))) {
            const float a0 = __expf(m0 - nm0), a1 = __expf(m1 - nm1);
            lacc[0] *= a0; lacc[1] *= a0; lacc[2] *= a1; lacc[3] *= a1;
#pragma unroll
            for (int df = 0; df < 8; df++) {
                oacc[df][0] *= a0; oacc[df][1] *= a0;
                oacc[df][2] *= a1; oacc[df][3] *= a1;
            }
            m0 = nm0; m1 = nm1;
        }
        const float mL0 = m0 * LOG2E, mL1 = m1 * LOG2E;

        // ---- P = ex2(s*log2e - m*log2e); O += P V; l += P·1 ----
#pragma unroll
        for (int t = 0; t < 4; t++) {
            uint32_t af[4];
            af[0] = ex2h2(packf16x2(fmaf(sacc[2*t][0],   LOG2E, -mL0),
                                    fmaf(sacc[2*t][1],   LOG2E, -mL0)));
            af[1] = ex2h2(packf16x2(fmaf(sacc[2*t][2],   LOG2E, -mL1),
                                    fmaf(sacc[2*t][3],   LOG2E, -mL1)));
            af[2] = ex2h2(packf16x2(fmaf(sacc[2*t+1][0], LOG2E, -mL0),
                                    fmaf(sacc[2*t+1][1], LOG2E, -mL0)));
            af[3] = ex2h2(packf16x2(fmaf(sacc[2*t+1][2], LOG2E, -mL1),
                                    fmaf(sacc[2*t+1][3], LOG2E, -mL1)));

            mma_f16(lacc, af, onesb);

            const int rpb = t * 8 + c;
#pragma unroll
            for (int df = 0; df < 8; df++) {
                const uint32_t* vh = &sVp[rpb * VP + df * 8 + g];
                uint32_t bfr[2];
                bfr[0] = vh[0];
                bfr[1] = vh[4 * VP];
                mma_f16(oacc[df], af, bfr);
            }
        }
    }

    asm volatile("cp.async.wait_group 0;");   // drain tail prefetches

    // ---- epilogue ----
    const float l0 = __shfl_sync(0xffffffffu, lacc[0], lane & ~3);
    const float l1 = __shfl_sync(0xffffffffu, lacc[2], lane & ~3);
    const float inv0 = 1.0f / l0;
    const float inv1 = 1.0f / l1;

    float* o0 = out + ((size_t)(b * Ss + r0) * Hh + h) * Dd;
    float* o1 = out + ((size_t)(b * Ss + r1) * Hh + h) * Dd;
#pragma unroll
    for (int df = 0; df < 8; df++) {
        const int dc = df * 8 + 2 * c;
        float2 w0, w1;
        w0.x = oacc[df][0] * inv0; w0.y = oacc[df][1] * inv0;
        w1.x = oacc[df][2] * inv1; w1.y = oacc[df][3] * inv1;
        *(float2*)(o0 + dc) = w0;
        *(float2*)(o1 + dc) = w1;
    }
}

} // namespace

extern "C" void kernel_launch(void* const* d_in, const int* in_sizes, int n_in,
                              void* d_out, int out_size)
{
    const float* q    = (const float*)d_in[0];
    const float* k    = (const float*)d_in[1];
    const float* v    = (const float*)d_in[2];
    const float* bias = (const float*)d_in[3];
    float* out        = (float*)d_out;

    cvt_kv_kernel<<<KBLKS + VBLKS, 256>>>(k, v);

    const dim3 grid(Bb * Hh * (Ss / BM));  // 2048 CTAs, batch fastest-varying
    fa_kernel<<<grid, 128>>>(q, bias, out);
}

// round 13
// speedup vs baseline: 1.0879x; 1.0014x over previous
#include <cuda_runtime.h>
#include <cuda_bf16.h>
#include <cuda_fp16.h>
#include <stdint.h>

namespace {

constexpr int Bb = 4, Ss = 2048, Hh = 16, Dd = 64;
constexpr int BM = 64, BN = 64;
constexpr int KP = 36;            // u32 per sK row: frag bank = 4g+c, conflict-free
constexpr int VP = 72;            // u32 per sV row-pair: frag bank = 8c+g, conflict-free
constexpr int NSTG = 3;           // pipeline depth
constexpr float SCALE = 0.125f;
constexpr float LOG2E = 1.4426950408889634f;
constexpr float NEGINF = -1e30f;

// fp16 scratch (pre-converted K/V), written by the fused pre-pass each call
__device__ __half   g_Kh[(size_t)Bb * Hh * Ss * Dd];        // [b][h][s][d]
__device__ uint32_t g_Vp[(size_t)Bb * Hh * (Ss/2) * Dd];    // [b][h][rp][d] f16x2(v[2rp],v[2rp+1])

__device__ __forceinline__ uint32_t packf16x2(float lo, float hi) {
    uint32_t r;
    asm("cvt.rn.f16x2.f32 %0, %1, %2;" : "=r"(r) : "f"(hi), "f"(lo));
    return r;
}
__device__ __forceinline__ uint32_t ex2h2(uint32_t x) {
    uint32_t r;
    asm("ex2.approx.f16x2 %0, %1;" : "=r"(r) : "r"(x));
    return r;
}
__device__ __forceinline__ uint32_t smem_u32(const void* p) {
    uint32_t a;
    asm("{ .reg .u64 t; cvta.to.shared.u64 t, %1; cvt.u32.u64 %0, t; }" : "=r"(a) : "l"(p));
    return a;
}
__device__ __forceinline__ void cpa16(uint32_t dst, const void* src) {
    asm volatile("cp.async.cg.shared.global [%0], [%1], 16;" :: "r"(dst), "l"(src));
}

__device__ __forceinline__ void mma_f16(float c[4], const uint32_t a[4], const uint32_t b[2]) {
    asm volatile(
        "mma.sync.aligned.m16n8k16.row.col.f32.f16.f16.f32 "
        "{%0,%1,%2,%3}, {%4,%5,%6,%7}, {%8,%9}, {%0,%1,%2,%3};"
        : "+f"(c[0]), "+f"(c[1]), "+f"(c[2]), "+f"(c[3])
        : "r"(a[0]), "r"(a[1]), "r"(a[2]), "r"(a[3]), "r"(b[0]), "r"(b[1]));
}

// ---- fused pre-pass: K -> fp16 [b][h][s][d]; V -> f16x2 row-pair [b][h][rp][d] ----
constexpr int KBLKS = (Bb * Hh * Ss * (Dd / 4)) / 256;        // 8192
constexpr int VBLKS = (Bb * Hh * (Ss / 2) * (Dd / 4)) / 256;  // 4096

__global__ void __launch_bounds__(256)
cvt_kv_kernel(const float* __restrict__ k, const float* __restrict__ v)
{
    if (blockIdx.x < KBLKS) {
        const int i   = blockIdx.x * 256 + threadIdx.x;
        const int d4i = i & 15;
        const int s   = (i >> 4) & 2047;
        const int h   = (i >> 15) & 15;
        const int b   = i >> 19;
        const float4 f = *(const float4*)(k + (((size_t)(b * Ss + s) * Hh + h) * Dd + d4i * 4));
        uint2 w;
        w.x = packf16x2(f.x, f.y);
        w.y = packf16x2(f.z, f.w);
        *(uint2*)(g_Kh + (((size_t)(b * Hh + h) * Ss + s) * Dd + d4i * 4)) = w;
    } else {
        const int i   = (blockIdx.x - KBLKS) * 256 + threadIdx.x;
        const int d4i = i & 15;
        const int rp  = (i >> 4) & 1023;
        const int h   = (i >> 14) & 15;
        const int b   = i >> 18;
        const float* base = v + (((size_t)(b * Ss + 2 * rp) * Hh + h) * Dd + d4i * 4);
        const float4 f0 = *(const float4*)(base);
        const float4 f1 = *(const float4*)(base + Hh * Dd);
        uint4 w;
        w.x = packf16x2(f0.x, f1.x);
        w.y = packf16x2(f0.y, f1.y);
        w.z = packf16x2(f0.z, f1.z);
        w.w = packf16x2(f0.w, f1.w);
        *(uint4*)(g_Vp + (((size_t)(b * Hh + h) * (Ss/2) + rp) * Dd + d4i * 4)) = w;
    }
}

// ---- main kernel: 4 CTAs/SM target ----
__global__ void __launch_bounds__(128, 4)
fa_kernel(const float* __restrict__ q, const float* __restrict__ bias,
          float* __restrict__ out)
{
    __shared__ __align__(16) uint32_t sK[NSTG][BN * KP];
    __shared__ __align__(16) uint32_t sV[NSTG][(BN/2) * VP];

    const int tid  = threadIdx.x;
    const int lane = tid & 31;
    const int wid  = tid >> 5;
    const int g    = lane >> 2;
    const int c    = lane & 3;

    const int idx = blockIdx.x;
    const int b   = idx & 3;
    const int h   = (idx >> 2) & 15;
    const int qt  = (Ss / BM - 1) - (idx >> 6);
    const int qrow = qt * BM;

    const int r0 = qrow + wid * 16 + g;
    const int r1 = r0 + 8;

    uint32_t sKa[NSTG], sVa[NSTG];
#pragma unroll
    for (int s = 0; s < NSTG; s++) { sKa[s] = smem_u32(&sK[s][0]); sVa[s] = smem_u32(&sV[s][0]); }

    const char* kbase = (const char*)(g_Kh + ((size_t)(b * Hh + h) * Ss) * Dd);
    const char* vbase = (const char*)(g_Vp + ((size_t)(b * Hh + h) * (Ss/2)) * Dd);

    // issue cp.async loads for tile jt into stage pb (one commit group)
    auto issue_tile = [&](int jt, int pb) {
        const char* kb = kbase + (size_t)jt * BN * Dd * 2;        // 64 rows x 128B
        const char* vb = vbase + (size_t)jt * (BN/2) * Dd * 4;    // 32 rps x 256B
#pragma unroll
        for (int it = 0; it < 4; it++) {
            const int gk = it * 128 + tid;
            const int n = gk >> 3, col = gk & 7;
            cpa16(sKa[pb] + n * 144 + col * 16, kb + n * 128 + col * 16);
        }
#pragma unroll
        for (int it = 0; it < 4; it++) {
            const int gv = it * 128 + tid;
            const int rp = gv >> 4, col = gv & 15;
            cpa16(sVa[pb] + rp * 288 + col * 16, vb + rp * 256 + col * 16);
        }
        asm volatile("cp.async.commit_group;");
    };

    // prologue: start tiles 0 and 1 (clamped)
    issue_tile(0, 0);
    issue_tile((qt >= 1) ? 1 : qt, 1 % NSTG);

    // ---- Q fragments: fp32 load + pack (once) ----
    uint32_t qa[4][4];
    {
        const float* q0 = q + ((size_t)(b * Ss + r0) * Hh + h) * Dd;
        const float* q1 = q + ((size_t)(b * Ss + r1) * Hh + h) * Dd;
#pragma unroll
        for (int ks = 0; ks < 4; ks++) {
            const int d0 = ks * 16 + 2 * c;
            const float2 a00 = *(const float2*)(q0 + d0);
            const float2 a01 = *(const float2*)(q1 + d0);
            const float2 a10 = *(const float2*)(q0 + d0 + 8);
            const float2 a11 = *(const float2*)(q1 + d0 + 8);
            qa[ks][0] = packf16x2(a00.x, a00.y);
            qa[ks][1] = packf16x2(a01.x, a01.y);
            qa[ks][2] = packf16x2(a10.x, a10.y);
            qa[ks][3] = packf16x2(a11.x, a11.y);
        }
    }

    float oacc[8][4];
#pragma unroll
    for (int i = 0; i < 8; i++) {
        oacc[i][0] = 0.f; oacc[i][1] = 0.f; oacc[i][2] = 0.f; oacc[i][3] = 0.f;
    }
    float lacc[4] = {0.f, 0.f, 0.f, 0.f};
    float m0 = NEGINF, m1 = NEGINF;

    const uint32_t onesw = (g == 0) ? 0x3C003C00u : 0u;
    const uint32_t onesb[2] = {onesw, onesw};

    const float* biasr0 = bias + ((size_t)h * Ss + r0) * Ss;
    const float* biasr1 = bias + ((size_t)h * Ss + r1) * Ss;

    for (int j = 0; j <= qt; j++) {
        const int p = j % NSTG;
        asm volatile("cp.async.wait_group 1;");   // tile j arrived (j+1 may be pending)
        __syncthreads();                          // stage (j+2)%NSTG free for reuse

        issue_tile((j + 2 <= qt) ? (j + 2) : qt, (j + 2) % NSTG);

        const uint32_t* sKp = sK[p];
        const uint32_t* sVp = sV[p];

        // ---- S = Q K^T ----
        float sacc[8][4];
#pragma unroll
        for (int nf = 0; nf < 8; nf++) {
            sacc[nf][0] = 0.f; sacc[nf][1] = 0.f; sacc[nf][2] = 0.f; sacc[nf][3] = 0.f;
#pragma unroll
            for (int ks = 0; ks < 4; ks++) {
                const uint32_t* kp = &sKp[(nf * 8 + g) * KP + ks * 8 + c];
                uint32_t bfr[2];
                bfr[0] = kp[0];
                bfr[1] = kp[4];
                mma_f16(sacc[nf], qa[ks], bfr);
            }
        }

        // ---- scale + bias (inline loads) + causal mask ----
        const int kcb = j * BN;
        const bool diag = (j == qt);
#pragma unroll
        for (int nf = 0; nf < 8; nf++) {
            const int kc = kcb + nf * 8 + 2 * c;
            const float2 bb0 = __ldg((const float2*)(biasr0 + kc));
            const float2 bb1 = __ldg((const float2*)(biasr1 + kc));
            sacc[nf][0] = sacc[nf][0] * SCALE + bb0.x;
            sacc[nf][1] = sacc[nf][1] * SCALE + bb0.y;
            sacc[nf][2] = sacc[nf][2] * SCALE + bb1.x;
            sacc[nf][3] = sacc[nf][3] * SCALE + bb1.y;
            if (diag) {
                if (kc     > r0) sacc[nf][0] = NEGINF;
                if (kc + 1 > r0) sacc[nf][1] = NEGINF;
                if (kc     > r1) sacc[nf][2] = NEGINF;
                if (kc + 1 > r1) sacc[nf][3] = NEGINF;
            }
        }

        // ---- online softmax: maxes ----
        float rm0 = NEGINF, rm1 = NEGINF;
#pragma unroll
        for (int nf = 0; nf < 8; nf++) {
            rm0 = fmaxf(rm0, fmaxf(sacc[nf][0], sacc[nf][1]));
            rm1 = fmaxf(rm1, fmaxf(sacc[nf][2], sacc[nf][3]));
        }
        rm0 = fmaxf(rm0, __shfl_xor_sync(0xffffffffu, rm0, 1));
        rm0 = fmaxf(rm0, __shfl_xor_sync(0xffffffffu, rm0, 2));
        rm1 = fmaxf(rm1, __shfl_xor_sync(0xffffffffu, rm1, 1));
        rm1 = fmaxf(rm1, __shfl_xor_sync(0xffffffffu, rm1, 2));

        const float nm0 = fmaxf(m0, rm0), nm1 = fmaxf(m1, rm1);

        // skip rescale when no lane's max moved (a==1 exactly -> identity)
        if (__any_sync(0xffffffffu, (nm0 > m0) | (nm1 > m1))) {
            const float a0 = __expf(m0 - nm0), a1 = __expf(m1 - nm1);
            lacc[0] *= a0; lacc[1] *= a0; lacc[2] *= a1; lacc[3] *= a1;
#pragma unroll
            for (int df = 0; df < 8; df++) {
                oacc[df][0] *= a0; oacc[df][1] *= a0;
                oacc[df][2] *= a1; oacc[df][3] *= a1;
            }
            m0 = nm0; m1 = nm1;
        }
        const float mL0 = m0 * LOG2E, mL1 = m1 * LOG2E;

        // ---- P = ex2(s*log2e - m*log2e); O += P V; l += P·1 ----
#pragma unroll
        for (int t = 0; t < 4; t++) {
            uint32_t af[4];
            af[0] = ex2h2(packf16x2(fmaf(sacc[2*t][0],   LOG2E, -mL0),
                                    fmaf(sacc[2*t][1],   LOG2E, -mL0)));
            af[1] = ex2h2(packf16x2(fmaf(sacc[2*t][2],   LOG2E, -mL1),
                                    fmaf(sacc[2*t][3],   LOG2E, -mL1)));
            af[2] = ex2h2(packf16x2(fmaf(sacc[2*t+1][0], LOG2E, -mL0),
                                    fmaf(sacc[2*t+1][1], LOG2E, -mL0)));
            af[3] = ex2h2(packf16x2(fmaf(sacc[2*t+1][2], LOG2E, -mL1),
                                    fmaf(sacc[2*t+1][3], LOG2E, -mL1)));

            mma_f16(lacc, af, onesb);

            const int rpb = t * 8 + c;
#pragma unroll
            for (int df = 0; df < 8; df++) {
                const uint32_t* vh = &sVp[rpb * VP + df * 8 + g];
                uint32_t bfr[2];
                bfr[0] = vh[0];
                bfr[1] = vh[4 * VP];
                mma_f16(oacc[df], af, bfr);
            }
        }
    }

    asm volatile("cp.async.wait_group 0;");   // drain tail prefetches

    // ---- epilogue ----
    const float l0 = __shfl_sync(0xffffffffu, lacc[0], lane & ~3);
    const float l1 = __shfl_sync(0xffffffffu, lacc[2], lane & ~3);
    const float inv0 = 1.0f / l0;
    const float inv1 = 1.0f / l1;

    float* o0 = out + ((size_t)(b * Ss + r0) * Hh + h) * Dd;
    float* o1 = out + ((size_t)(b * Ss + r1) * Hh + h) * Dd;
#pragma unroll
    for (int df = 0; df < 8; df++) {
        const int dc = df * 8 + 2 * c;
        float2 w0, w1;
        w0.x = oacc[df][0] * inv0; w0.y = oacc[df][1] * inv0;
        w1.x = oacc[df][2] * inv1; w1.y = oacc[df][3] * inv1;
        *(float2*)(o0 + dc) = w0;
        *(float2*)(o1 + dc) = w1;
    }
}

} // namespace

extern "C" void kernel_launch(void* const* d_in, const int* in_sizes, int n_in,
                              void* d_out, int out_size)
{
    const float* q    = (const float*)d_in[0];
    const float* k    = (const float*)d_in[1];
    const float* v    = (const float*)d_in[2];
    const float* bias = (const float*)d_in[3];
    float* out        = (float*)d_out;

    cvt_kv_kernel<<<KBLKS + VBLKS, 256>>>(k, v);

    const dim3 grid(Bb * Hh * (Ss / BM));  // 2048 CTAs, batch fastest-varying
    fa_kernel<<<grid, 128>>>(q, bias, out);
}

// round 14
// speedup vs baseline: 1.1336x; 1.0420x over previous
#include <cuda_runtime.h>
#include <cuda_bf16.h>
#include <cuda_fp16.h>
#include <stdint.h>

namespace {

constexpr int Bb = 4, Ss = 2048, Hh = 16, Dd = 64;
constexpr int BM = 64, BN = 64;
constexpr int KP = 36;            // u32 per sK row: frag bank = 4g+c, conflict-free
constexpr int VP = 72;            // u32 per sV row-pair: frag bank = 8c+g, conflict-free
constexpr int NSTG = 3;           // pipeline depth
constexpr float SCALE = 0.125f;
constexpr float LOG2E = 1.4426950408889634f;
constexpr float NEGINF = -1e30f;

// fp16 scratch (pre-converted K/V), written by the fused pre-pass each call
__device__ __half   g_Kh[(size_t)Bb * Hh * Ss * Dd];        // [b][h][s][d]
__device__ uint32_t g_Vp[(size_t)Bb * Hh * (Ss/2) * Dd];    // [b][h][rp][d] f16x2(v[2rp],v[2rp+1])

__device__ __forceinline__ uint32_t packf16x2(float lo, float hi) {
    uint32_t r;
    asm("cvt.rn.f16x2.f32 %0, %1, %2;" : "=r"(r) : "f"(hi), "f"(lo));
    return r;
}
__device__ __forceinline__ uint32_t ex2h2(uint32_t x) {
    uint32_t r;
    asm("ex2.approx.f16x2 %0, %1;" : "=r"(r) : "r"(x));
    return r;
}
__device__ __forceinline__ uint32_t smem_u32(const void* p) {
    uint32_t a;
    asm("{ .reg .u64 t; cvta.to.shared.u64 t, %1; cvt.u32.u64 %0, t; }" : "=r"(a) : "l"(p));
    return a;
}
__device__ __forceinline__ void cpa16(uint32_t dst, const void* src) {
    asm volatile("cp.async.cg.shared.global [%0], [%1], 16;" :: "r"(dst), "l"(src));
}

__device__ __forceinline__ void mma_f16(float c[4], const uint32_t a[4], const uint32_t b[2]) {
    asm volatile(
        "mma.sync.aligned.m16n8k16.row.col.f32.f16.f16.f32 "
        "{%0,%1,%2,%3}, {%4,%5,%6,%7}, {%8,%9}, {%0,%1,%2,%3};"
        : "+f"(c[0]), "+f"(c[1]), "+f"(c[2]), "+f"(c[3])
        : "r"(a[0]), "r"(a[1]), "r"(a[2]), "r"(a[3]), "r"(b[0]), "r"(b[1]));
}

// ---- fused pre-pass: K -> fp16 [b][h][s][d]; V -> f16x2 row-pair [b][h][rp][d] ----
constexpr int KBLKS = (Bb * Hh * Ss * (Dd / 4)) / 256;        // 8192
constexpr int VBLKS = (Bb * Hh * (Ss / 2) * (Dd / 4)) / 256;  // 4096

__global__ void __launch_bounds__(256)
cvt_kv_kernel(const float* __restrict__ k, const float* __restrict__ v)
{
    if (blockIdx.x < KBLKS) {
        const int i   = blockIdx.x * 256 + threadIdx.x;
        const int d4i = i & 15;
        const int s   = (i >> 4) & 2047;
        const int h   = (i >> 15) & 15;
        const int b   = i >> 19;
        const float4 f = *(const float4*)(k + (((size_t)(b * Ss + s) * Hh + h) * Dd + d4i * 4));
        uint2 w;
        w.x = packf16x2(f.x, f.y);
        w.y = packf16x2(f.z, f.w);
        *(uint2*)(g_Kh + (((size_t)(b * Hh + h) * Ss + s) * Dd + d4i * 4)) = w;
    } else {
        const int i   = (blockIdx.x - KBLKS) * 256 + threadIdx.x;
        const int d4i = i & 15;
        const int rp  = (i >> 4) & 1023;
        const int h   = (i >> 14) & 15;
        const int b   = i >> 18;
        const float* base = v + (((size_t)(b * Ss + 2 * rp) * Hh + h) * Dd + d4i * 4);
        const float4 f0 = *(const float4*)(base);
        const float4 f1 = *(const float4*)(base + Hh * Dd);
        uint4 w;
        w.x = packf16x2(f0.x, f1.x);
        w.y = packf16x2(f0.y, f1.y);
        w.z = packf16x2(f0.z, f1.z);
        w.w = packf16x2(f0.w, f1.w);
        *(uint4*)(g_Vp + (((size_t)(b * Hh + h) * (Ss/2) + rp) * Dd + d4i * 4)) = w;
    }
}

// ---- main kernel: 4 CTAs/SM ----
__global__ void __launch_bounds__(128, 4)
fa_kernel(const float* __restrict__ q, const float* __restrict__ bias,
          float* __restrict__ out)
{
    __shared__ __align__(16) uint32_t sK[NSTG][BN * KP];
    __shared__ __align__(16) uint32_t sV[NSTG][(BN/2) * VP];

    const int tid  = threadIdx.x;
    const int lane = tid & 31;
    const int wid  = tid >> 5;
    const int g    = lane >> 2;
    const int c    = lane & 3;

    const int idx = blockIdx.x;
    const int b   = idx & 3;
    const int h   = (idx >> 2) & 15;
    const int qt  = (Ss / BM - 1) - (idx >> 6);
    const int qrow = qt * BM;

    const int r0 = qrow + wid * 16 + g;
    const int r1 = r0 + 8;

    uint32_t sKa[NSTG], sVa[NSTG];
#pragma unroll
    for (int s = 0; s < NSTG; s++) { sKa[s] = smem_u32(&sK[s][0]); sVa[s] = smem_u32(&sV[s][0]); }

    const char* kbase = (const char*)(g_Kh + ((size_t)(b * Hh + h) * Ss) * Dd);
    const char* vbase = (const char*)(g_Vp + ((size_t)(b * Hh + h) * (Ss/2)) * Dd);

    // issue cp.async loads for tile jt into stage pb (one commit group)
    auto issue_tile = [&](int jt, int pb) {
        const char* kb = kbase + (size_t)jt * BN * Dd * 2;        // 64 rows x 128B
        const char* vb = vbase + (size_t)jt * (BN/2) * Dd * 4;    // 32 rps x 256B
#pragma unroll
        for (int it = 0; it < 4; it++) {
            const int gk = it * 128 + tid;
            const int n = gk >> 3, col = gk & 7;
            cpa16(sKa[pb] + n * 144 + col * 16, kb + n * 128 + col * 16);
        }
#pragma unroll
        for (int it = 0; it < 4; it++) {
            const int gv = it * 128 + tid;
            const int rp = gv >> 4, col = gv & 15;
            cpa16(sVa[pb] + rp * 288 + col * 16, vb + rp * 256 + col * 16);
        }
        asm volatile("cp.async.commit_group;");
    };

    // prologue: start tiles 0 and 1 (clamped)
    issue_tile(0, 0);
    issue_tile((qt >= 1) ? 1 : qt, 1 % NSTG);

    // ---- Q fragments: fp32 load + pack (once) ----
    uint32_t qa[4][4];
    {
        const float* q0 = q + ((size_t)(b * Ss + r0) * Hh + h) * Dd;
        const float* q1 = q + ((size_t)(b * Ss + r1) * Hh + h) * Dd;
#pragma unroll
        for (int ks = 0; ks < 4; ks++) {
            const int d0 = ks * 16 + 2 * c;
            const float2 a00 = *(const float2*)(q0 + d0);
            const float2 a01 = *(const float2*)(q1 + d0);
            const float2 a10 = *(const float2*)(q0 + d0 + 8);
            const float2 a11 = *(const float2*)(q1 + d0 + 8);
            qa[ks][0] = packf16x2(a00.x, a00.y);
            qa[ks][1] = packf16x2(a01.x, a01.y);
            qa[ks][2] = packf16x2(a10.x, a10.y);
            qa[ks][3] = packf16x2(a11.x, a11.y);
        }
    }

    float oacc[8][4];
#pragma unroll
    for (int i = 0; i < 8; i++) {
        oacc[i][0] = 0.f; oacc[i][1] = 0.f; oacc[i][2] = 0.f; oacc[i][3] = 0.f;
    }
    float lacc[4] = {0.f, 0.f, 0.f, 0.f};
    float m0 = NEGINF, m1 = NEGINF;

    const uint32_t onesw = (g == 0) ? 0x3C003C00u : 0u;
    const uint32_t onesb[2] = {onesw, onesw};

    // bias row pointers as advancing float2 pointers (immediate offsets in the loop)
    const float2* bp0 = (const float2*)(bias + ((size_t)h * Ss + r0) * Ss) + c;
    const float2* bp1 = (const float2*)(bias + ((size_t)h * Ss + r1) * Ss) + c;

    for (int j = 0; j <= qt; j++) {
        const int p = j % NSTG;
        asm volatile("cp.async.wait_group 1;");   // tile j arrived (j+1 may be pending)
        __syncthreads();                          // stage (j+2)%NSTG free for reuse

        issue_tile((j + 2 <= qt) ? (j + 2) : qt, (j + 2) % NSTG);

        const uint32_t* sKp = sK[p];
        const uint32_t* sVp = sV[p];

        // ---- S = Q K^T ----
        float sacc[8][4];
#pragma unroll
        for (int nf = 0; nf < 8; nf++) {
            sacc[nf][0] = 0.f; sacc[nf][1] = 0.f; sacc[nf][2] = 0.f; sacc[nf][3] = 0.f;
#pragma unroll
            for (int ks = 0; ks < 4; ks++) {
                const uint32_t* kp = &sKp[(nf * 8 + g) * KP + ks * 8 + c];
                uint32_t bfr[2];
                bfr[0] = kp[0];
                bfr[1] = kp[4];
                mma_f16(sacc[nf], qa[ks], bfr);
            }
        }

        // ---- scale + bias (immediate-offset loads) ----
#pragma unroll
        for (int nf = 0; nf < 8; nf++) {
            const float2 bb0 = __ldg(bp0 + nf * 4);
            const float2 bb1 = __ldg(bp1 + nf * 4);
            sacc[nf][0] = sacc[nf][0] * SCALE + bb0.x;
            sacc[nf][1] = sacc[nf][1] * SCALE + bb0.y;
            sacc[nf][2] = sacc[nf][2] * SCALE + bb1.x;
            sacc[nf][3] = sacc[nf][3] * SCALE + bb1.y;
        }
        bp0 += BN / 2;   // advance one tile (64 floats = 32 float2)
        bp1 += BN / 2;

        // ---- causal mask: only the diagonal tile ----
        if (j == qt) {
            const int kcb = j * BN;
#pragma unroll
            for (int nf = 0; nf < 8; nf++) {
                const int kc = kcb + nf * 8 + 2 * c;
                if (kc     > r0) sacc[nf][0] = NEGINF;
                if (kc + 1 > r0) sacc[nf][1] = NEGINF;
                if (kc     > r1) sacc[nf][2] = NEGINF;
                if (kc + 1 > r1) sacc[nf][3] = NEGINF;
            }
        }

        // ---- online softmax: maxes ----
        float rm0 = NEGINF, rm1 = NEGINF;
#pragma unroll
        for (int nf = 0; nf < 8; nf++) {
            rm0 = fmaxf(rm0, fmaxf(sacc[nf][0], sacc[nf][1]));
            rm1 = fmaxf(rm1, fmaxf(sacc[nf][2], sacc[nf][3]));
        }
        rm0 = fmaxf(rm0, __shfl_xor_sync(0xffffffffu, rm0, 1));
        rm0 = fmaxf(rm0, __shfl_xor_sync(0xffffffffu, rm0, 2));
        rm1 = fmaxf(rm1, __shfl_xor_sync(0xffffffffu, rm1, 1));
        rm1 = fmaxf(rm1, __shfl_xor_sync(0xffffffffu, rm1, 2));

        const float nm0 = fmaxf(m0, rm0), nm1 = fmaxf(m1, rm1);

        // skip rescale when no lane's max moved (a==1 exactly -> identity)
        if (__any_sync(0xffffffffu, (nm0 > m0) | (nm1 > m1))) {
            const float a0 = __expf(m0 - nm0), a1 = __expf(m1 - nm1);
            lacc[0] *= a0; lacc[1] *= a0; lacc[2] *= a1; lacc[3] *= a1;
#pragma unroll
            for (int df = 0; df < 8; df++) {
                oacc[df][0] *= a0; oacc[df][1] *= a0;
                oacc[df][2] *= a1; oacc[df][3] *= a1;
            }
            m0 = nm0; m1 = nm1;
        }
        const float mL0 = m0 * LOG2E, mL1 = m1 * LOG2E;

        // ---- P = ex2(s*log2e - m*log2e); O += P V; l += P·1 ----
#pragma unroll
        for (int t = 0; t < 4; t++) {
            uint32_t af[4];
            af[0] = ex2h2(packf16x2(fmaf(sacc[2*t][0],   LOG2E, -mL0),
                                    fmaf(sacc[2*t][1],   LOG2E, -mL0)));
            af[1] = ex2h2(packf16x2(fmaf(sacc[2*t][2],   LOG2E, -mL1),
                                    fmaf(sacc[2*t][3],   LOG2E, -mL1)));
            af[2] = ex2h2(packf16x2(fmaf(sacc[2*t+1][0], LOG2E, -mL0),
                                    fmaf(sacc[2*t+1][1], LOG2E, -mL0)));
            af[3] = ex2h2(packf16x2(fmaf(sacc[2*t+1][2], LOG2E, -mL1),
                                    fmaf(sacc[2*t+1][3], LOG2E, -mL1)));

            mma_f16(lacc, af, onesb);

            const int rpb = t * 8 + c;
#pragma unroll
            for (int df = 0; df < 8; df++) {
                const uint32_t* vh = &sVp[rpb * VP + df * 8 + g];
                uint32_t bfr[2];
                bfr[0] = vh[0];
                bfr[1] = vh[4 * VP];
                mma_f16(oacc[df], af, bfr);
            }
        }
    }

    asm volatile("cp.async.wait_group 0;");   // drain tail prefetches

    // ---- epilogue ----
    const float l0 = __shfl_sync(0xffffffffu, lacc[0], lane & ~3);
    const float l1 = __shfl_sync(0xffffffffu, lacc[2], lane & ~3);
    const float inv0 = 1.0f / l0;
    const float inv1 = 1.0f / l1;

    float* o0 = out + ((size_t)(b * Ss + r0) * Hh + h) * Dd;
    float* o1 = out + ((size_t)(b * Ss + r1) * Hh + h) * Dd;
#pragma unroll
    for (int df = 0; df < 8; df++) {
        const int dc = df * 8 + 2 * c;
        float2 w0, w1;
        w0.x = oacc[df][0] * inv0; w0.y = oacc[df][1] * inv0;
        w1.x = oacc[df][2] * inv1; w1.y = oacc[df][3] * inv1;
        *(float2*)(o0 + dc) = w0;
        *(float2*)(o1 + dc) = w1;
    }
}

} // namespace

extern "C" void kernel_launch(void* const* d_in, const int* in_sizes, int n_in,
                              void* d_out, int out_size)
{
    const float* q    = (const float*)d_in[0];
    const float* k    = (const float*)d_in[1];
    const float* v    = (const float*)d_in[2];
    const float* bias = (const float*)d_in[3];
    float* out        = (float*)d_out;

    cvt_kv_kernel<<<KBLKS + VBLKS, 256>>>(k, v);

    const dim3 grid(Bb * Hh * (Ss / BM));  // 2048 CTAs, batch fastest-varying
    fa_kernel<<<grid, 128>>>(q, bias, out);
}

// round 15
// speedup vs baseline: 1.1573x; 1.0209x over previous
#include <cuda_runtime.h>
#include <cuda_bf16.h>
#include <cuda_fp16.h>
#include <stdint.h>

namespace {

constexpr int Bb = 4, Ss = 2048, Hh = 16, Dd = 64;
constexpr int BM = 64, BN = 64;
constexpr int KP = 36;            // u32 per sK row: frag bank = 4g+c, conflict-free
constexpr int VP = 72;            // u32 per sV row-pair: frag bank = 8c+g, conflict-free
constexpr int NSTG = 3;           // pipeline depth
constexpr float SCALE = 0.125f;
constexpr float LOG2E = 1.4426950408889634f;
constexpr float QSCALE = SCALE * LOG2E;      // folded into Q at pack time
constexpr float MARGINL = 2.0f * LOG2E;      // +2 nats overflow margin on the frozen shift
constexpr float NEGINF = -1e30f;

// fp16 scratch (pre-converted K/V), written by the fused pre-pass each call
__device__ __half   g_Kh[(size_t)Bb * Hh * Ss * Dd];        // [b][h][s][d]
__device__ uint32_t g_Vp[(size_t)Bb * Hh * (Ss/2) * Dd];    // [b][h][rp][d] f16x2(v[2rp],v[2rp+1])

__device__ __forceinline__ uint32_t packf16x2(float lo, float hi) {
    uint32_t r;
    asm("cvt.rn.f16x2.f32 %0, %1, %2;" : "=r"(r) : "f"(hi), "f"(lo));
    return r;
}
__device__ __forceinline__ uint32_t ex2h2(uint32_t x) {
    uint32_t r;
    asm("ex2.approx.f16x2 %0, %1;" : "=r"(r) : "r"(x));
    return r;
}
__device__ __forceinline__ uint32_t smem_u32(const void* p) {
    uint32_t a;
    asm("{ .reg .u64 t; cvta.to.shared.u64 t, %1; cvt.u32.u64 %0, t; }" : "=r"(a) : "l"(p));
    return a;
}
__device__ __forceinline__ void cpa16(uint32_t dst, const void* src) {
    asm volatile("cp.async.cg.shared.global [%0], [%1], 16;" :: "r"(dst), "l"(src));
}

__device__ __forceinline__ void mma_f16(float c[4], const uint32_t a[4], const uint32_t b[2]) {
    asm volatile(
        "mma.sync.aligned.m16n8k16.row.col.f32.f16.f16.f32 "
        "{%0,%1,%2,%3}, {%4,%5,%6,%7}, {%8,%9}, {%0,%1,%2,%3};"
        : "+f"(c[0]), "+f"(c[1]), "+f"(c[2]), "+f"(c[3])
        : "r"(a[0]), "r"(a[1]), "r"(a[2]), "r"(a[3]), "r"(b[0]), "r"(b[1]));
}

// ---- fused pre-pass: K -> fp16 [b][h][s][d]; V -> f16x2 row-pair [b][h][rp][d] ----
constexpr int KBLKS = (Bb * Hh * Ss * (Dd / 4)) / 256;        // 8192
constexpr int VBLKS = (Bb * Hh * (Ss / 2) * (Dd / 4)) / 256;  // 4096

__global__ void __launch_bounds__(256)
cvt_kv_kernel(const float* __restrict__ k, const float* __restrict__ v)
{
    if (blockIdx.x < KBLKS) {
        const int i   = blockIdx.x * 256 + threadIdx.x;
        const int d4i = i & 15;
        const int s   = (i >> 4) & 2047;
        const int h   = (i >> 15) & 15;
        const int b   = i >> 19;
        const float4 f = *(const float4*)(k + (((size_t)(b * Ss + s) * Hh + h) * Dd + d4i * 4));
        uint2 w;
        w.x = packf16x2(f.x, f.y);
        w.y = packf16x2(f.z, f.w);
        *(uint2*)(g_Kh + (((size_t)(b * Hh + h) * Ss + s) * Dd + d4i * 4)) = w;
    } else {
        const int i   = (blockIdx.x - KBLKS) * 256 + threadIdx.x;
        const int d4i = i & 15;
        const int rp  = (i >> 4) & 1023;
        const int h   = (i >> 14) & 15;
        const int b   = i >> 18;
        const float* base = v + (((size_t)(b * Ss + 2 * rp) * Hh + h) * Dd + d4i * 4);
        const float4 f0 = *(const float4*)(base);
        const float4 f1 = *(const float4*)(base + Hh * Dd);
        uint4 w;
        w.x = packf16x2(f0.x, f1.x);
        w.y = packf16x2(f0.y, f1.y);
        w.z = packf16x2(f0.z, f1.z);
        w.w = packf16x2(f0.w, f1.w);
        *(uint4*)(g_Vp + (((size_t)(b * Hh + h) * (Ss/2) + rp) * Dd + d4i * 4)) = w;
    }
}

// ---- main kernel: 4 CTAs/SM, frozen-shift softmax ----
__global__ void __launch_bounds__(128, 4)
fa_kernel(const float* __restrict__ q, const float* __restrict__ bias,
          float* __restrict__ out)
{
    __shared__ __align__(16) uint32_t sK[NSTG][BN * KP];
    __shared__ __align__(16) uint32_t sV[NSTG][(BN/2) * VP];

    const int tid  = threadIdx.x;
    const int lane = tid & 31;
    const int wid  = tid >> 5;
    const int g    = lane >> 2;
    const int c    = lane & 3;

    const int idx = blockIdx.x;
    const int b   = idx & 3;
    const int h   = (idx >> 2) & 15;
    const int qt  = (Ss / BM - 1) - (idx >> 6);
    const int qrow = qt * BM;

    const int r0 = qrow + wid * 16 + g;
    const int r1 = r0 + 8;

    uint32_t sKa[NSTG], sVa[NSTG];
#pragma unroll
    for (int s = 0; s < NSTG; s++) { sKa[s] = smem_u32(&sK[s][0]); sVa[s] = smem_u32(&sV[s][0]); }

    const char* kbase = (const char*)(g_Kh + ((size_t)(b * Hh + h) * Ss) * Dd);
    const char* vbase = (const char*)(g_Vp + ((size_t)(b * Hh + h) * (Ss/2)) * Dd);

    // issue cp.async loads for tile jt into stage pb (one commit group)
    auto issue_tile = [&](int jt, int pb) {
        const char* kb = kbase + (size_t)jt * BN * Dd * 2;        // 64 rows x 128B
        const char* vb = vbase + (size_t)jt * (BN/2) * Dd * 4;    // 32 rps x 256B
#pragma unroll
        for (int it = 0; it < 4; it++) {
            const int gk = it * 128 + tid;
            const int n = gk >> 3, col = gk & 7;
            cpa16(sKa[pb] + n * 144 + col * 16, kb + n * 128 + col * 16);
        }
#pragma unroll
        for (int it = 0; it < 4; it++) {
            const int gv = it * 128 + tid;
            const int rp = gv >> 4, col = gv & 15;
            cpa16(sVa[pb] + rp * 288 + col * 16, vb + rp * 256 + col * 16);
        }
        asm volatile("cp.async.commit_group;");
    };

    // prologue: start tiles 0 and 1 (clamped)
    issue_tile(0, 0);
    issue_tile((qt >= 1) ? 1 : qt, 1 % NSTG);

    // ---- Q fragments: fp32 load, scale by SCALE*LOG2E, pack (once) ----
    uint32_t qa[4][4];
    {
        const float* q0 = q + ((size_t)(b * Ss + r0) * Hh + h) * Dd;
        const float* q1 = q + ((size_t)(b * Ss + r1) * Hh + h) * Dd;
#pragma unroll
        for (int ks = 0; ks < 4; ks++) {
            const int d0 = ks * 16 + 2 * c;
            const float2 a00 = *(const float2*)(q0 + d0);
            const float2 a01 = *(const float2*)(q1 + d0);
            const float2 a10 = *(const float2*)(q0 + d0 + 8);
            const float2 a11 = *(const float2*)(q1 + d0 + 8);
            qa[ks][0] = packf16x2(a00.x * QSCALE, a00.y * QSCALE);
            qa[ks][1] = packf16x2(a01.x * QSCALE, a01.y * QSCALE);
            qa[ks][2] = packf16x2(a10.x * QSCALE, a10.y * QSCALE);
            qa[ks][3] = packf16x2(a11.x * QSCALE, a11.y * QSCALE);
        }
    }

    float oacc[8][4];
#pragma unroll
    for (int i = 0; i < 8; i++) {
        oacc[i][0] = 0.f; oacc[i][1] = 0.f; oacc[i][2] = 0.f; oacc[i][3] = 0.f;
    }
    float lacc[4] = {0.f, 0.f, 0.f, 0.f};
    float mL0 = 0.f, mL1 = 0.f;   // frozen shift (log2 domain), set at j==0

    const uint32_t onesw = (g == 0) ? 0x3C003C00u : 0u;
    const uint32_t onesb[2] = {onesw, onesw};

    // bias row pointers as advancing float2 pointers (immediate offsets in the loop)
    const float2* bp0 = (const float2*)(bias + ((size_t)h * Ss + r0) * Ss) + c;
    const float2* bp1 = (const float2*)(bias + ((size_t)h * Ss + r1) * Ss) + c;

    for (int j = 0; j <= qt; j++) {
        const int p = j % NSTG;
        asm volatile("cp.async.wait_group 1;");   // tile j arrived (j+1 may be pending)
        __syncthreads();                          // stage (j+2)%NSTG free for reuse

        issue_tile((j + 2 <= qt) ? (j + 2) : qt, (j + 2) % NSTG);

        const uint32_t* sKp = sK[p];
        const uint32_t* sVp = sV[p];

        // ---- S_log2 = (Q*scale*log2e) K^T - mL  (shift baked into accumulator init) ----
        const float in0 = (j == 0) ? 0.f : -mL0;
        const float in1 = (j == 0) ? 0.f : -mL1;
        float sacc[8][4];
#pragma unroll
        for (int nf = 0; nf < 8; nf++) {
            sacc[nf][0] = in0; sacc[nf][1] = in0; sacc[nf][2] = in1; sacc[nf][3] = in1;
#pragma unroll
            for (int ks = 0; ks < 4; ks++) {
                const uint32_t* kp = &sKp[(nf * 8 + g) * KP + ks * 8 + c];
                uint32_t bfr[2];
                bfr[0] = kp[0];
                bfr[1] = kp[4];
                mma_f16(sacc[nf], qa[ks], bfr);
            }
        }

        // ---- bias (log2 domain, immediate-offset loads) ----
#pragma unroll
        for (int nf = 0; nf < 8; nf++) {
            const float2 bb0 = __ldg(bp0 + nf * 4);
            const float2 bb1 = __ldg(bp1 + nf * 4);
            sacc[nf][0] = fmaf(bb0.x, LOG2E, sacc[nf][0]);
            sacc[nf][1] = fmaf(bb0.y, LOG2E, sacc[nf][1]);
            sacc[nf][2] = fmaf(bb1.x, LOG2E, sacc[nf][2]);
            sacc[nf][3] = fmaf(bb1.y, LOG2E, sacc[nf][3]);
        }
        bp0 += BN / 2;
        bp1 += BN / 2;

        // ---- causal mask: only the diagonal tile ----
        if (j == qt) {
            const int kcb = j * BN;
#pragma unroll
            for (int nf = 0; nf < 8; nf++) {
                const int kc = kcb + nf * 8 + 2 * c;
                if (kc     > r0) sacc[nf][0] = NEGINF;
                if (kc + 1 > r0) sacc[nf][1] = NEGINF;
                if (kc     > r1) sacc[nf][2] = NEGINF;
                if (kc + 1 > r1) sacc[nf][3] = NEGINF;
            }
        }

        // ---- j==0: freeze the shift from this tile's row max (+ margin), apply it ----
        if (j == 0) {
            float rm0 = NEGINF, rm1 = NEGINF;
#pragma unroll
            for (int nf = 0; nf < 8; nf++) {
                rm0 = fmaxf(rm0, fmaxf(sacc[nf][0], sacc[nf][1]));
                rm1 = fmaxf(rm1, fmaxf(sacc[nf][2], sacc[nf][3]));
            }
            rm0 = fmaxf(rm0, __shfl_xor_sync(0xffffffffu, rm0, 1));
            rm0 = fmaxf(rm0, __shfl_xor_sync(0xffffffffu, rm0, 2));
            rm1 = fmaxf(rm1, __shfl_xor_sync(0xffffffffu, rm1, 1));
            rm1 = fmaxf(rm1, __shfl_xor_sync(0xffffffffu, rm1, 2));
            mL0 = rm0 + MARGINL;
            mL1 = rm1 + MARGINL;
#pragma unroll
            for (int nf = 0; nf < 8; nf++) {
                sacc[nf][0] -= mL0; sacc[nf][1] -= mL0;
                sacc[nf][2] -= mL1; sacc[nf][3] -= mL1;
            }
        }

        // ---- P = ex2(sacc) fp16; O += P V; l += P·1 ----
#pragma unroll
        for (int t = 0; t < 4; t++) {
            uint32_t af[4];
            af[0] = ex2h2(packf16x2(sacc[2*t][0],   sacc[2*t][1]));
            af[1] = ex2h2(packf16x2(sacc[2*t][2],   sacc[2*t][3]));
            af[2] = ex2h2(packf16x2(sacc[2*t+1][0], sacc[2*t+1][1]));
            af[3] = ex2h2(packf16x2(sacc[2*t+1][2], sacc[2*t+1][3]));

            mma_f16(lacc, af, onesb);

            const int rpb = t * 8 + c;
#pragma unroll
            for (int df = 0; df < 8; df++) {
                const uint32_t* vh = &sVp[rpb * VP + df * 8 + g];
                uint32_t bfr[2];
                bfr[0] = vh[0];
                bfr[1] = vh[4 * VP];
                mma_f16(oacc[df], af, bfr);
            }
        }
    }

    asm volatile("cp.async.wait_group 0;");   // drain tail prefetches

    // ---- epilogue ----
    const float l0 = __shfl_sync(0xffffffffu, lacc[0], lane & ~3);
    const float l1 = __shfl_sync(0xffffffffu, lacc[2], lane & ~3);
    const float inv0 = 1.0f / l0;
    const float inv1 = 1.0f / l1;

    float* o0 = out + ((size_t)(b * Ss + r0) * Hh + h) * Dd;
    float* o1 = out + ((size_t)(b * Ss + r1) * Hh + h) * Dd;
#pragma unroll
    for (int df = 0; df < 8; df++) {
        const int dc = df * 8 + 2 * c;
        float2 w0, w1;
        w0.x = oacc[df][0] * inv0; w0.y = oacc[df][1] * inv0;
        w1.x = oacc[df][2] * inv1; w1.y = oacc[df][3] * inv1;
        *(float2*)(o0 + dc) = w0;
        *(float2*)(o1 + dc) = w1;
    }
}

} // namespace

extern "C" void kernel_launch(void* const* d_in, const int* in_sizes, int n_in,
                              void* d_out, int out_size)
{
    const float* q    = (const float*)d_in[0];
    const float* k    = (const float*)d_in[1];
    const float* v    = (const float*)d_in[2];
    const float* bias = (const float*)d_in[3];
    float* out        = (float*)d_out;

    cvt_kv_kernel<<<KBLKS + VBLKS, 256>>>(k, v);

    const dim3 grid(Bb * Hh * (Ss / BM));  // 2048 CTAs, batch fastest-varying
    fa_kernel<<<grid, 128>>>(q, bias, out);
}

// round 16
// speedup vs baseline: 1.3048x; 1.1274x over previous
#include <cuda_runtime.h>
#include <cuda_bf16.h>
#include <cuda_fp16.h>
#include <stdint.h>

namespace {

constexpr int Bb = 4, Ss = 2048, Hh = 16, Dd = 64;
constexpr int BM = 128, BN = 64;
constexpr int KP = 36;            // u32 per sK row: frag bank = 4g+c, conflict-free
constexpr int VP = 72;            // u32 per sV row-pair: frag bank = 8c+g, conflict-free
constexpr int NSTG = 3;           // pipeline depth
constexpr float SCALE = 0.125f;
constexpr float LOG2E = 1.4426950408889634f;
constexpr float QSCALE = SCALE * LOG2E;      // folded into Q at pack time
constexpr float MARGINL = 2.0f * LOG2E;      // +2 nats overflow margin on the frozen shift
constexpr float NEGINF = -1e30f;

// fp16 scratch (pre-converted K/V), written by the fused pre-pass each call
__device__ __half   g_Kh[(size_t)Bb * Hh * Ss * Dd];        // [b][h][s][d]
__device__ uint32_t g_Vp[(size_t)Bb * Hh * (Ss/2) * Dd];    // [b][h][rp][d] f16x2(v[2rp],v[2rp+1])

__device__ __forceinline__ uint32_t packf16x2(float lo, float hi) {
    uint32_t r;
    asm("cvt.rn.f16x2.f32 %0, %1, %2;" : "=r"(r) : "f"(hi), "f"(lo));
    return r;
}
__device__ __forceinline__ uint32_t ex2h2(uint32_t x) {
    uint32_t r;
    asm("ex2.approx.f16x2 %0, %1;" : "=r"(r) : "r"(x));
    return r;
}
__device__ __forceinline__ uint32_t smem_u32(const void* p) {
    uint32_t a;
    asm("{ .reg .u64 t; cvta.to.shared.u64 t, %1; cvt.u32.u64 %0, t; }" : "=r"(a) : "l"(p));
    return a;
}
__device__ __forceinline__ void cpa16(uint32_t dst, const void* src) {
    asm volatile("cp.async.cg.shared.global [%0], [%1], 16;" :: "r"(dst), "l"(src));
}

__device__ __forceinline__ void mma_f16(float c[4], const uint32_t a[4], const uint32_t b[2]) {
    asm volatile(
        "mma.sync.aligned.m16n8k16.row.col.f32.f16.f16.f32 "
        "{%0,%1,%2,%3}, {%4,%5,%6,%7}, {%8,%9}, {%0,%1,%2,%3};"
        : "+f"(c[0]), "+f"(c[1]), "+f"(c[2]), "+f"(c[3])
        : "r"(a[0]), "r"(a[1]), "r"(a[2]), "r"(a[3]), "r"(b[0]), "r"(b[1]));
}

// ---- fused pre-pass: K -> fp16 [b][h][s][d]; V -> f16x2 row-pair [b][h][rp][d] ----
constexpr int KBLKS = (Bb * Hh * Ss * (Dd / 4)) / 256;        // 8192
constexpr int VBLKS = (Bb * Hh * (Ss / 2) * (Dd / 4)) / 256;  // 4096

__global__ void __launch_bounds__(256)
cvt_kv_kernel(const float* __restrict__ k, const float* __restrict__ v)
{
    if (blockIdx.x < KBLKS) {
        const int i   = blockIdx.x * 256 + threadIdx.x;
        const int d4i = i & 15;
        const int s   = (i >> 4) & 2047;
        const int h   = (i >> 15) & 15;
        const int b   = i >> 19;
        const float4 f = *(const float4*)(k + (((size_t)(b * Ss + s) * Hh + h) * Dd + d4i * 4));
        uint2 w;
        w.x = packf16x2(f.x, f.y);
        w.y = packf16x2(f.z, f.w);
        *(uint2*)(g_Kh + (((size_t)(b * Hh + h) * Ss + s) * Dd + d4i * 4)) = w;
    } else {
        const int i   = (blockIdx.x - KBLKS) * 256 + threadIdx.x;
        const int d4i = i & 15;
        const int rp  = (i >> 4) & 1023;
        const int h   = (i >> 14) & 15;
        const int b   = i >> 18;
        const float* base = v + (((size_t)(b * Ss + 2 * rp) * Hh + h) * Dd + d4i * 4);
        const float4 f0 = *(const float4*)(base);
        const float4 f1 = *(const float4*)(base + Hh * Dd);
        uint4 w;
        w.x = packf16x2(f0.x, f1.x);
        w.y = packf16x2(f0.y, f1.y);
        w.z = packf16x2(f0.z, f1.z);
        w.w = packf16x2(f0.w, f1.w);
        *(uint4*)(g_Vp + (((size_t)(b * Hh + h) * (Ss/2) + rp) * Dd + d4i * 4)) = w;
    }
}

// ---- main kernel: BM=128, chunk-fused QK->P->PV, frozen-shift softmax ----
__global__ void __launch_bounds__(128, 3)
fa_kernel(const float* __restrict__ q, const float* __restrict__ bias,
          float* __restrict__ out)
{
    __shared__ __align__(16) uint32_t sK[NSTG][BN * KP];
    __shared__ __align__(16) uint32_t sV[NSTG][(BN/2) * VP];

    const int tid  = threadIdx.x;
    const int lane = tid & 31;
    const int wid  = tid >> 5;
    const int g    = lane >> 2;
    const int c    = lane & 3;

    const int idx = blockIdx.x;
    const int b   = idx & 3;
    const int h   = (idx >> 2) & 15;
    const int qt  = (Ss / BM - 1) - (idx >> 6);
    const int qrow = qt * BM;

    // each warp owns 32 rows: two m16 row blocks
    const int rw  = qrow + wid * 32 + g;
    const int r00 = rw,      r01 = rw + 8;
    const int r10 = rw + 16, r11 = rw + 24;
    const int nj  = 2 * qt + 2;

    uint32_t sKa[NSTG], sVa[NSTG];
#pragma unroll
    for (int s = 0; s < NSTG; s++) { sKa[s] = smem_u32(&sK[s][0]); sVa[s] = smem_u32(&sV[s][0]); }

    const char* kbase = (const char*)(g_Kh + ((size_t)(b * Hh + h) * Ss) * Dd);
    const char* vbase = (const char*)(g_Vp + ((size_t)(b * Hh + h) * (Ss/2)) * Dd);

    auto issue_tile = [&](int jt, int pb) {
        const char* kb = kbase + (size_t)jt * BN * Dd * 2;
        const char* vb = vbase + (size_t)jt * (BN/2) * Dd * 4;
#pragma unroll
        for (int it = 0; it < 4; it++) {
            const int gk = it * 128 + tid;
            const int n = gk >> 3, col = gk & 7;
            cpa16(sKa[pb] + n * 144 + col * 16, kb + n * 128 + col * 16);
        }
#pragma unroll
        for (int it = 0; it < 4; it++) {
            const int gv = it * 128 + tid;
            const int rp = gv >> 4, col = gv & 15;
            cpa16(sVa[pb] + rp * 288 + col * 16, vb + rp * 256 + col * 16);
        }
        asm volatile("cp.async.commit_group;");
    };

    issue_tile(0, 0);
    issue_tile(1, 1);   // nj >= 2 always

    // ---- Q fragments: fp32 load, scale by SCALE*LOG2E, pack (once) ----
    uint32_t qa[2][4][4];
    {
        const float* q00 = q + ((size_t)(b * Ss + r00) * Hh + h) * Dd;
        const float* q01 = q + ((size_t)(b * Ss + r01) * Hh + h) * Dd;
        const float* q10 = q + ((size_t)(b * Ss + r10) * Hh + h) * Dd;
        const float* q11 = q + ((size_t)(b * Ss + r11) * Hh + h) * Dd;
#pragma unroll
        for (int ks = 0; ks < 4; ks++) {
            const int d0 = ks * 16 + 2 * c;
            float2 x;
            x = *(const float2*)(q00 + d0);     qa[0][ks][0] = packf16x2(x.x * QSCALE, x.y * QSCALE);
            x = *(const float2*)(q01 + d0);     qa[0][ks][1] = packf16x2(x.x * QSCALE, x.y * QSCALE);
            x = *(const float2*)(q00 + d0 + 8); qa[0][ks][2] = packf16x2(x.x * QSCALE, x.y * QSCALE);
            x = *(const float2*)(q01 + d0 + 8); qa[0][ks][3] = packf16x2(x.x * QSCALE, x.y * QSCALE);
            x = *(const float2*)(q10 + d0);     qa[1][ks][0] = packf16x2(x.x * QSCALE, x.y * QSCALE);
            x = *(const float2*)(q11 + d0);     qa[1][ks][1] = packf16x2(x.x * QSCALE, x.y * QSCALE);
            x = *(const float2*)(q10 + d0 + 8); qa[1][ks][2] = packf16x2(x.x * QSCALE, x.y * QSCALE);
            x = *(const float2*)(q11 + d0 + 8); qa[1][ks][3] = packf16x2(x.x * QSCALE, x.y * QSCALE);
        }
    }

    float oacc[2][8][4];
#pragma unroll
    for (int rb = 0; rb < 2; rb++)
#pragma unroll
        for (int i = 0; i < 8; i++) {
            oacc[rb][i][0] = 0.f; oacc[rb][i][1] = 0.f;
            oacc[rb][i][2] = 0.f; oacc[rb][i][3] = 0.f;
        }
    float lacc0[4] = {0.f, 0.f, 0.f, 0.f};
    float lacc1[4] = {0.f, 0.f, 0.f, 0.f};
    float mL00, mL01, mL10, mL11;   // frozen shifts (log2 domain), set at j==0

    const uint32_t onesw = (g == 0) ? 0x3C003C00u : 0u;
    const uint32_t onesb[2] = {onesw, onesw};

    const float2* bp00 = (const float2*)(bias + ((size_t)h * Ss + r00) * Ss) + c;
    const float2* bp01 = (const float2*)(bias + ((size_t)h * Ss + r01) * Ss) + c;
    const float2* bp10 = (const float2*)(bias + ((size_t)h * Ss + r10) * Ss) + c;
    const float2* bp11 = (const float2*)(bias + ((size_t)h * Ss + r11) * Ss) + c;

    // ================= j = 0 peel: full tile, compute frozen shift =================
    {
        asm volatile("cp.async.wait_group 1;");
        __syncthreads();
        issue_tile((2 < nj) ? 2 : (nj - 1), 2);

        const uint32_t* sKp = sK[0];
        const uint32_t* sVp = sV[0];

        float sacc[2][8][4];
#pragma unroll
        for (int nf = 0; nf < 8; nf++) {
            sacc[0][nf][0] = 0.f; sacc[0][nf][1] = 0.f; sacc[0][nf][2] = 0.f; sacc[0][nf][3] = 0.f;
            sacc[1][nf][0] = 0.f; sacc[1][nf][1] = 0.f; sacc[1][nf][2] = 0.f; sacc[1][nf][3] = 0.f;
#pragma unroll
            for (int ks = 0; ks < 4; ks++) {
                const uint32_t* kp = &sKp[(nf * 8 + g) * KP + ks * 8 + c];
                uint32_t bfr[2];
                bfr[0] = kp[0];
                bfr[1] = kp[4];
                mma_f16(sacc[0][nf], qa[0][ks], bfr);
                mma_f16(sacc[1][nf], qa[1][ks], bfr);
            }
        }
#pragma unroll
        for (int nf = 0; nf < 8; nf++) {
            const float2 bb00 = __ldg(bp00 + nf * 4);
            const float2 bb01 = __ldg(bp01 + nf * 4);
            const float2 bb10 = __ldg(bp10 + nf * 4);
            const float2 bb11 = __ldg(bp11 + nf * 4);
            sacc[0][nf][0] = fmaf(bb00.x, LOG2E, sacc[0][nf][0]);
            sacc[0][nf][1] = fmaf(bb00.y, LOG2E, sacc[0][nf][1]);
            sacc[0][nf][2] = fmaf(bb01.x, LOG2E, sacc[0][nf][2]);
            sacc[0][nf][3] = fmaf(bb01.y, LOG2E, sacc[0][nf][3]);
            sacc[1][nf][0] = fmaf(bb10.x, LOG2E, sacc[1][nf][0]);
            sacc[1][nf][1] = fmaf(bb10.y, LOG2E, sacc[1][nf][1]);
            sacc[1][nf][2] = fmaf(bb11.x, LOG2E, sacc[1][nf][2]);
            sacc[1][nf][3] = fmaf(bb11.y, LOG2E, sacc[1][nf][3]);
        }
        bp00 += BN / 2; bp01 += BN / 2; bp10 += BN / 2; bp11 += BN / 2;

        if (qt == 0) {   // tile 0 is diagonal only when qt==0
#pragma unroll
            for (int nf = 0; nf < 8; nf++) {
                const int kc = nf * 8 + 2 * c;
                if (kc     > r00) sacc[0][nf][0] = NEGINF;
                if (kc + 1 > r00) sacc[0][nf][1] = NEGINF;
                if (kc     > r01) sacc[0][nf][2] = NEGINF;
                if (kc + 1 > r01) sacc[0][nf][3] = NEGINF;
                if (kc     > r10) sacc[1][nf][0] = NEGINF;
                if (kc + 1 > r10) sacc[1][nf][1] = NEGINF;
                if (kc     > r11) sacc[1][nf][2] = NEGINF;
                if (kc + 1 > r11) sacc[1][nf][3] = NEGINF;
            }
        }

        float rm00 = NEGINF, rm01 = NEGINF, rm10 = NEGINF, rm11 = NEGINF;
#pragma unroll
        for (int nf = 0; nf < 8; nf++) {
            rm00 = fmaxf(rm00, fmaxf(sacc[0][nf][0], sacc[0][nf][1]));
            rm01 = fmaxf(rm01, fmaxf(sacc[0][nf][2], sacc[0][nf][3]));
            rm10 = fmaxf(rm10, fmaxf(sacc[1][nf][0], sacc[1][nf][1]));
            rm11 = fmaxf(rm11, fmaxf(sacc[1][nf][2], sacc[1][nf][3]));
        }
        rm00 = fmaxf(rm00, __shfl_xor_sync(0xffffffffu, rm00, 1));
        rm00 = fmaxf(rm00, __shfl_xor_sync(0xffffffffu, rm00, 2));
        rm01 = fmaxf(rm01, __shfl_xor_sync(0xffffffffu, rm01, 1));
        rm01 = fmaxf(rm01, __shfl_xor_sync(0xffffffffu, rm01, 2));
        rm10 = fmaxf(rm10, __shfl_xor_sync(0xffffffffu, rm10, 1));
        rm10 = fmaxf(rm10, __shfl_xor_sync(0xffffffffu, rm10, 2));
        rm11 = fmaxf(rm11, __shfl_xor_sync(0xffffffffu, rm11, 1));
        rm11 = fmaxf(rm11, __shfl_xor_sync(0xffffffffu, rm11, 2));
        mL00 = rm00 + MARGINL; mL01 = rm01 + MARGINL;
        mL10 = rm10 + MARGINL; mL11 = rm11 + MARGINL;

#pragma unroll
        for (int t = 0; t < 4; t++) {
            uint32_t af0[4], af1[4];
            af0[0] = ex2h2(packf16x2(sacc[0][2*t][0]   - mL00, sacc[0][2*t][1]   - mL00));
            af0[1] = ex2h2(packf16x2(sacc[0][2*t][2]   - mL01, sacc[0][2*t][3]   - mL01));
            af0[2] = ex2h2(packf16x2(sacc[0][2*t+1][0] - mL00, sacc[0][2*t+1][1] - mL00));
            af0[3] = ex2h2(packf16x2(sacc[0][2*t+1][2] - mL01, sacc[0][2*t+1][3] - mL01));
            af1[0] = ex2h2(packf16x2(sacc[1][2*t][0]   - mL10, sacc[1][2*t][1]   - mL10));
            af1[1] = ex2h2(packf16x2(sacc[1][2*t][2]   - mL11, sacc[1][2*t][3]   - mL11));
            af1[2] = ex2h2(packf16x2(sacc[1][2*t+1][0] - mL10, sacc[1][2*t+1][1] - mL10));
            af1[3] = ex2h2(packf16x2(sacc[1][2*t+1][2] - mL11, sacc[1][2*t+1][3] - mL11));

            mma_f16(lacc0, af0, onesb);
            mma_f16(lacc1, af1, onesb);

            const int rpb = t * 8 + c;
#pragma unroll
            for (int df = 0; df < 8; df++) {
                const uint32_t* vh = &sVp[rpb * VP + df * 8 + g];
                uint32_t bfr[2];
                bfr[0] = vh[0];
                bfr[1] = vh[4 * VP];
                mma_f16(oacc[0][df], af0, bfr);
                mma_f16(oacc[1][df], af1, bfr);
            }
        }
    }

    // ================= j >= 1: chunk-fused QK -> P -> PV =================
    for (int j = 1; j < nj; j++) {
        const int p = j % NSTG;
        asm volatile("cp.async.wait_group 1;");
        __syncthreads();
        issue_tile((j + 2 < nj) ? (j + 2) : (nj - 1), (j + 2) % NSTG);

        const uint32_t* sKp = sK[p];
        const uint32_t* sVp = sV[p];
        const bool diag = (j >= 2 * qt);
        const int kcb = j * BN;

#pragma unroll
        for (int t = 0; t < 4; t++) {
            // sacc chunk: nf = 2t, 2t+1 for both row blocks (16 regs live)
            float s00[4], s01[4], s10[4], s11[4];   // [rb][e]
            s00[0] = -mL00; s00[1] = -mL00; s00[2] = -mL01; s00[3] = -mL01;
            s01[0] = -mL00; s01[1] = -mL00; s01[2] = -mL01; s01[3] = -mL01;
            s10[0] = -mL10; s10[1] = -mL10; s10[2] = -mL11; s10[3] = -mL11;
            s11[0] = -mL10; s11[1] = -mL10; s11[2] = -mL11; s11[3] = -mL11;
#pragma unroll
            for (int ks = 0; ks < 4; ks++) {
                const uint32_t* kp0 = &sKp[((2*t)   * 8 + g) * KP + ks * 8 + c];
                const uint32_t* kp1 = &sKp[((2*t+1) * 8 + g) * KP + ks * 8 + c];
                uint32_t b0[2], b1[2];
                b0[0] = kp0[0]; b0[1] = kp0[4];
                b1[0] = kp1[0]; b1[1] = kp1[4];
                mma_f16(s00, qa[0][ks], b0);
                mma_f16(s01, qa[0][ks], b1);
                mma_f16(s10, qa[1][ks], b0);
                mma_f16(s11, qa[1][ks], b1);
            }
            {
                const float2 ba00 = __ldg(bp00 + (2*t) * 4);
                const float2 ba01 = __ldg(bp01 + (2*t) * 4);
                const float2 ba10 = __ldg(bp10 + (2*t) * 4);
                const float2 ba11 = __ldg(bp11 + (2*t) * 4);
                const float2 bb00 = __ldg(bp00 + (2*t+1) * 4);
                const float2 bb01 = __ldg(bp01 + (2*t+1) * 4);
                const float2 bb10 = __ldg(bp10 + (2*t+1) * 4);
                const float2 bb11 = __ldg(bp11 + (2*t+1) * 4);
                s00[0] = fmaf(ba00.x, LOG2E, s00[0]); s00[1] = fmaf(ba00.y, LOG2E, s00[1]);
                s00[2] = fmaf(ba01.x, LOG2E, s00[2]); s00[3] = fmaf(ba01.y, LOG2E, s00[3]);
                s01[0] = fmaf(bb00.x, LOG2E, s01[0]); s01[1] = fmaf(bb00.y, LOG2E, s01[1]);
                s01[2] = fmaf(bb01.x, LOG2E, s01[2]); s01[3] = fmaf(bb01.y, LOG2E, s01[3]);
                s10[0] = fmaf(ba10.x, LOG2E, s10[0]); s10[1] = fmaf(ba10.y, LOG2E, s10[1]);
                s10[2] = fmaf(ba11.x, LOG2E, s10[2]); s10[3] = fmaf(ba11.y, LOG2E, s10[3]);
                s11[0] = fmaf(bb10.x, LOG2E, s11[0]); s11[1] = fmaf(bb10.y, LOG2E, s11[1]);
                s11[2] = fmaf(bb11.x, LOG2E, s11[2]); s11[3] = fmaf(bb11.y, LOG2E, s11[3]);
            }
            if (diag) {
                const int kc0 = kcb + (2*t)   * 8 + 2 * c;
                const int kc1 = kcb + (2*t+1) * 8 + 2 * c;
                if (kc0     > r00) s00[0] = NEGINF;
                if (kc0 + 1 > r00) s00[1] = NEGINF;
                if (kc0     > r01) s00[2] = NEGINF;
                if (kc0 + 1 > r01) s00[3] = NEGINF;
                if (kc1     > r00) s01[0] = NEGINF;
                if (kc1 + 1 > r00) s01[1] = NEGINF;
                if (kc1     > r01) s01[2] = NEGINF;
                if (kc1 + 1 > r01) s01[3] = NEGINF;
                if (kc0     > r10) s10[0] = NEGINF;
                if (kc0 + 1 > r10) s10[1] = NEGINF;
                if (kc0     > r11) s10[2] = NEGINF;
                if (kc0 + 1 > r11) s10[3] = NEGINF;
                if (kc1     > r10) s11[0] = NEGINF;
                if (kc1 + 1 > r10) s11[1] = NEGINF;
                if (kc1     > r11) s11[2] = NEGINF;
                if (kc1 + 1 > r11) s11[3] = NEGINF;
            }

            uint32_t af0[4], af1[4];
            af0[0] = ex2h2(packf16x2(s00[0], s00[1]));
            af0[1] = ex2h2(packf16x2(s00[2], s00[3]));
            af0[2] = ex2h2(packf16x2(s01[0], s01[1]));
            af0[3] = ex2h2(packf16x2(s01[2], s01[3]));
            af1[0] = ex2h2(packf16x2(s10[0], s10[1]));
            af1[1] = ex2h2(packf16x2(s10[2], s10[3]));
            af1[2] = ex2h2(packf16x2(s11[0], s11[1]));
            af1[3] = ex2h2(packf16x2(s11[2], s11[3]));

            mma_f16(lacc0, af0, onesb);
            mma_f16(lacc1, af1, onesb);

            const int rpb = t * 8 + c;
#pragma unroll
            for (int df = 0; df < 8; df++) {
                const uint32_t* vh = &sVp[rpb * VP + df * 8 + g];
                uint32_t bfr[2];
                bfr[0] = vh[0];
                bfr[1] = vh[4 * VP];
                mma_f16(oacc[0][df], af0, bfr);
                mma_f16(oacc[1][df], af1, bfr);
            }
        }
        bp00 += BN / 2; bp01 += BN / 2; bp10 += BN / 2; bp11 += BN / 2;
    }

    asm volatile("cp.async.wait_group 0;");

    // ---- epilogue ----
    const float l00 = __shfl_sync(0xffffffffu, lacc0[0], lane & ~3);
    const float l01 = __shfl_sync(0xffffffffu, lacc0[2], lane & ~3);
    const float l10 = __shfl_sync(0xffffffffu, lacc1[0], lane & ~3);
    const float l11 = __shfl_sync(0xffffffffu, lacc1[2], lane & ~3);
    const float i00 = 1.0f / l00, i01 = 1.0f / l01;
    const float i10 = 1.0f / l10, i11 = 1.0f / l11;

    float* o00 = out + ((size_t)(b * Ss + r00) * Hh + h) * Dd;
    float* o01 = out + ((size_t)(b * Ss + r01) * Hh + h) * Dd;
    float* o10 = out + ((size_t)(b * Ss + r10) * Hh + h) * Dd;
    float* o11 = out + ((size_t)(b * Ss + r11) * Hh + h) * Dd;
#pragma unroll
    for (int df = 0; df < 8; df++) {
        const int dc = df * 8 + 2 * c;
        float2 w;
        w.x = oacc[0][df][0] * i00; w.y = oacc[0][df][1] * i00; *(float2*)(o00 + dc) = w;
        w.x = oacc[0][df][2] * i01; w.y = oacc[0][df][3] * i01; *(float2*)(o01 + dc) = w;
        w.x = oacc[1][df][0] * i10; w.y = oacc[1][df][1] * i10; *(float2*)(o10 + dc) = w;
        w.x = oacc[1][df][2] * i11; w.y = oacc[1][df][3] * i11; *(float2*)(o11 + dc) = w;
    }
}

} // namespace

extern "C" void kernel_launch(void* const* d_in, const int* in_sizes, int n_in,
                              void* d_out, int out_size)
{
    const float* q    = (const float*)d_in[0];
    const float* k    = (const float*)d_in[1];
    const float* v    = (const float*)d_in[2];
    const float* bias = (const float*)d_in[3];
    float* out        = (float*)d_out;

    cvt_kv_kernel<<<KBLKS + VBLKS, 256>>>(k, v);

    const dim3 grid(Bb * Hh * (Ss / BM));  // 1024 CTAs, batch fastest-varying
    fa_kernel<<<grid, 128>>>(q, bias, out);
}